// round 1
// baseline (speedup 1.0000x reference)
#include <cuda_runtime.h>
#include <cstdint>

#define L_SEQ 8192
#define D_IN  512
#define O_OUT 1024
#define BATCH 8

// Scratch (device-global: allocation-free per harness rules)
__device__ float g_fb[(size_t)BATCH * O_OUT * L_SEQ];   // 256 MB
__device__ float g_wn_hi[O_OUT * D_IN];
__device__ float g_wn_lo[O_OUT * D_IN];

__device__ __forceinline__ uint32_t f2tf32(float v) {
    uint32_t u;
    asm("cvt.rna.tf32.f32 %0, %1;" : "=r"(u) : "f"(v));
    return u;
}

// ---------------------------------------------------------------------------
// Kernel 1: normalize W rows, split into tf32 hi/lo
// ---------------------------------------------------------------------------
__global__ void normalize_w_kernel(const float* __restrict__ W) {
    int o = blockIdx.x;          // 1024 rows
    int tid = threadIdx.x;       // 128 threads
    const float* row = W + (size_t)o * D_IN;
    float s = 0.f;
    for (int i = tid; i < D_IN; i += 128) { float w = row[i]; s = fmaf(w, w, s); }
    #pragma unroll
    for (int off = 16; off; off >>= 1) s += __shfl_xor_sync(0xffffffffu, s, off);
    __shared__ float red[4];
    if ((tid & 31) == 0) red[tid >> 5] = s;
    __syncthreads();
    float tot = red[0] + red[1] + red[2] + red[3];
    // Wn = W / (EPS + ||W||/sqrt(fan)) / sqrt(fan) = W / (EPS*sqrt(fan) + ||W||)
    float inv = 1.0f / (1e-4f * sqrtf((float)D_IN) + sqrtf(tot));
    for (int i = tid; i < D_IN; i += 128) {
        float wn = row[i] * inv;
        uint32_t hu = f2tf32(wn);
        float hi = __uint_as_float(hu);
        uint32_t lu = f2tf32(wn - hi);
        g_wn_hi[(size_t)o * D_IN + i] = hi;
        g_wn_lo[(size_t)o * D_IN + i] = __uint_as_float(lu);
    }
}

// ---------------------------------------------------------------------------
// Kernel 2: GEMM fb = Wn @ x  (3xTF32 via mma.sync m16n8k8)
// Block tile 128x128, K-step 16, 512 threads (4x4 warps, warp tile 32x32)
// ---------------------------------------------------------------------------
#define BM 128
#define BN 128
#define BK 16
#define APAD 20    // stride pad -> conflict-free fragment LDS
#define BPAD 136

__device__ __forceinline__ void mma_tf32(float* c, const uint32_t* a, const uint32_t* b) {
    asm("mma.sync.aligned.m16n8k8.row.col.f32.tf32.tf32.f32 "
        "{%0,%1,%2,%3}, {%4,%5,%6,%7}, {%8,%9}, {%0,%1,%2,%3};"
        : "+f"(c[0]), "+f"(c[1]), "+f"(c[2]), "+f"(c[3])
        : "r"(a[0]), "r"(a[1]), "r"(a[2]), "r"(a[3]), "r"(b[0]), "r"(b[1]));
}

__global__ void __launch_bounds__(512, 1) gemm_kernel(const float* __restrict__ x) {
    __shared__ float As_hi[BM][APAD];
    __shared__ float As_lo[BM][APAD];
    __shared__ float Bs_hi[BK][BPAD];
    __shared__ float Bs_lo[BK][BPAD];

    const int tid  = threadIdx.x;
    const int lane = tid & 31;
    const int warp = tid >> 5;
    const int warpM = warp >> 2;   // 0..3
    const int warpN = warp & 3;    // 0..3
    const int b  = blockIdx.z;
    const int m0 = blockIdx.y * BM;
    const int n0 = blockIdx.x * BN;
    const float* xb = x + (size_t)b * D_IN * L_SEQ;

    float acc[2][4][4];
    #pragma unroll
    for (int mt = 0; mt < 2; mt++)
        #pragma unroll
        for (int nt = 0; nt < 4; nt++)
            #pragma unroll
            for (int i = 0; i < 4; i++) acc[mt][nt][i] = 0.f;

    // load mapping
    const int ar  = tid >> 2;      // A row 0..127
    const int akq = tid & 3;       // A k-quad
    const int bk  = tid >> 5;      // B k-row 0..15
    const int bnq = tid & 31;      // B n-quad

    const float* aHiPtr = g_wn_hi + (size_t)(m0 + ar) * D_IN + akq * 4;
    const float* aLoPtr = g_wn_lo + (size_t)(m0 + ar) * D_IN + akq * 4;

    float4 aHiR = *(const float4*)(aHiPtr);
    float4 aLoR = *(const float4*)(aLoPtr);
    float4 bR   = *(const float4*)(xb + (size_t)bk * L_SEQ + n0 + bnq * 4);

    const int r = lane >> 2;
    const int c = lane & 3;

    #pragma unroll 1
    for (int k0 = 0; k0 < D_IN; k0 += BK) {
        // stage current tiles
        *(float4*)&As_hi[ar][akq * 4] = aHiR;
        *(float4*)&As_lo[ar][akq * 4] = aLoR;
        {
            float4 bh, bl;
            uint32_t u;
            u = f2tf32(bR.x); bh.x = __uint_as_float(u); bl.x = __uint_as_float(f2tf32(bR.x - bh.x));
            u = f2tf32(bR.y); bh.y = __uint_as_float(u); bl.y = __uint_as_float(f2tf32(bR.y - bh.y));
            u = f2tf32(bR.z); bh.z = __uint_as_float(u); bl.z = __uint_as_float(f2tf32(bR.z - bh.z));
            u = f2tf32(bR.w); bh.w = __uint_as_float(u); bl.w = __uint_as_float(f2tf32(bR.w - bh.w));
            *(float4*)&Bs_hi[bk][bnq * 4] = bh;
            *(float4*)&Bs_lo[bk][bnq * 4] = bl;
        }
        __syncthreads();

        // prefetch next iteration (latency covered by compute below)
        int k1 = k0 + BK;
        if (k1 < D_IN) {
            aHiR = *(const float4*)(aHiPtr + k1);
            aLoR = *(const float4*)(aLoPtr + k1);
            bR   = *(const float4*)(xb + (size_t)(k1 + bk) * L_SEQ + n0 + bnq * 4);
        }

        #pragma unroll
        for (int kk = 0; kk < BK; kk += 8) {
            uint32_t ah[2][4], al[2][4], bhf[4][2], blf[4][2];
            #pragma unroll
            for (int mt = 0; mt < 2; mt++) {
                int row = warpM * 32 + mt * 16 + r;
                ah[mt][0] = __float_as_uint(As_hi[row    ][kk + c    ]);
                ah[mt][1] = __float_as_uint(As_hi[row + 8][kk + c    ]);
                ah[mt][2] = __float_as_uint(As_hi[row    ][kk + c + 4]);
                ah[mt][3] = __float_as_uint(As_hi[row + 8][kk + c + 4]);
                al[mt][0] = __float_as_uint(As_lo[row    ][kk + c    ]);
                al[mt][1] = __float_as_uint(As_lo[row + 8][kk + c    ]);
                al[mt][2] = __float_as_uint(As_lo[row    ][kk + c + 4]);
                al[mt][3] = __float_as_uint(As_lo[row + 8][kk + c + 4]);
            }
            #pragma unroll
            for (int nt = 0; nt < 4; nt++) {
                int col = warpN * 32 + nt * 8 + r;
                bhf[nt][0] = __float_as_uint(Bs_hi[kk + c    ][col]);
                bhf[nt][1] = __float_as_uint(Bs_hi[kk + c + 4][col]);
                blf[nt][0] = __float_as_uint(Bs_lo[kk + c    ][col]);
                blf[nt][1] = __float_as_uint(Bs_lo[kk + c + 4][col]);
            }
            #pragma unroll
            for (int mt = 0; mt < 2; mt++)
                #pragma unroll
                for (int nt = 0; nt < 4; nt++) {
                    mma_tf32(acc[mt][nt], ah[mt], bhf[nt]);  // hi*hi
                    mma_tf32(acc[mt][nt], ah[mt], blf[nt]);  // hi*lo
                    mma_tf32(acc[mt][nt], al[mt], bhf[nt]);  // lo*hi
                }
        }
        __syncthreads();
    }

    // epilogue -> g_fb
    float* fbb = g_fb + (size_t)b * O_OUT * L_SEQ;
    #pragma unroll
    for (int mt = 0; mt < 2; mt++)
        #pragma unroll
        for (int nt = 0; nt < 4; nt++) {
            int row = m0 + warpM * 32 + mt * 16 + r;
            int col = n0 + warpN * 32 + nt * 8 + 2 * c;
            float2 v0 = make_float2(acc[mt][nt][0], acc[mt][nt][1]);
            float2 v1 = make_float2(acc[mt][nt][2], acc[mt][nt][3]);
            *(float2*)&fbb[(size_t)row * L_SEQ + col]       = v0;
            *(float2*)&fbb[(size_t)(row + 8) * L_SEQ + col] = v1;
        }
}

// ---------------------------------------------------------------------------
// Kernel 3: parallel linear-recurrence scan (fwd + bwd), H_t = a*H_{t-1} + v
// One block per (batch, dir, channel): 4096 blocks x 256 threads.
// Per segment of 1024: thread composes 4 contiguous elems, warp shuffle scan,
// cross-warp compose via smem totals, carry chained across 8 segments.
// ---------------------------------------------------------------------------
__device__ __forceinline__ void gate(float h, float g, float& a, float& v) {
    float en = expf(-fabsf(g));                 // e^{-|g|}
    float q  = rsqrtf(fmaf(en, en, 1.0f));      // 1/sqrt(1+en^2)
    float eq = en * q;
    bool pos = (g >= 0.f);
    a = pos ? eq : q;           // sigma(-g)*sqrt(1+sech g)
    v = (pos ? q : eq) * h;     // sigma(g)*sqrt(1+sech g)*h
}

__global__ void __launch_bounds__(256) scan_kernel(float* __restrict__ out) {
    const int sid = blockIdx.x;            // 0..4095
    const int b   = sid >> 9;
    const int rem = sid & 511;
    const int dir = rem >> 8;              // 0 fwd, 1 bwd
    const int ch  = rem & 255;

    const float* hp = g_fb + ((size_t)b * O_OUT + (size_t)dir * 512 + ch) * L_SEQ;
    const float* gp = hp + (size_t)256 * L_SEQ;
    float* op = out + ((size_t)b * 512 + (size_t)dir * 256 + ch) * L_SEQ;

    const int tid = threadIdx.x;
    const int lane = tid & 31;
    const int warp = tid >> 5;

    __shared__ float totA[8], totV[8];
    float carryH = 0.f;

    #pragma unroll 1
    for (int s = 0; s < L_SEQ / 1024; ++s) {
        const int base = s * 1024 + tid * 4;   // logical position of this thread's 4 elems
        float4 h4, g4;
        if (dir == 0) {
            h4 = *(const float4*)(hp + base);
            g4 = *(const float4*)(gp + base);
        } else {
            int gi = L_SEQ - 4 - base;
            float4 th = *(const float4*)(hp + gi);
            float4 tg = *(const float4*)(gp + gi);
            h4 = make_float4(th.w, th.z, th.y, th.x);
            g4 = make_float4(tg.w, tg.z, tg.y, tg.x);
        }

        float a[4], v[4];
        gate(h4.x, g4.x, a[0], v[0]);
        gate(h4.y, g4.y, a[1], v[1]);
        gate(h4.z, g4.z, a[2], v[2]);
        gate(h4.w, g4.w, a[3], v[3]);

        // local compose over 4 sequential elements
        float A = a[0], V = v[0];
        #pragma unroll
        for (int i = 1; i < 4; i++) { V = fmaf(a[i], V, v[i]); A *= a[i]; }

        // warp inclusive scan (compose op)
        #pragma unroll
        for (int off = 1; off < 32; off <<= 1) {
            float Au = __shfl_up_sync(0xffffffffu, A, off);
            float Vu = __shfl_up_sync(0xffffffffu, V, off);
            if (lane >= off) { V = fmaf(A, Vu, V); A *= Au; }
        }
        if (lane == 31) { totA[warp] = A; totV[warp] = V; }
        __syncthreads();

        // hidden state entering this warp's region
        float Hp = carryH;
        for (int j = 0; j < warp; j++) Hp = fmaf(totA[j], Hp, totV[j]);

        // lane-exclusive prefix -> state entering this thread's 4 elems
        float Ae = __shfl_up_sync(0xffffffffu, A, 1);
        float Ve = __shfl_up_sync(0xffffffffu, V, 1);
        float H = (lane == 0) ? Hp : fmaf(Ae, Hp, Ve);

        float o0, o1, o2, o3;
        H = fmaf(a[0], H, v[0]); o0 = H;
        H = fmaf(a[1], H, v[1]); o1 = H;
        H = fmaf(a[2], H, v[2]); o2 = H;
        H = fmaf(a[3], H, v[3]); o3 = H;

        if (dir == 0) {
            *(float4*)(op + base) = make_float4(o0, o1, o2, o3);
        } else {
            *(float4*)(op + (L_SEQ - 4 - base)) = make_float4(o3, o2, o1, o0);
        }

        // advance carry over whole 1024-segment
        float Hc = carryH;
        #pragma unroll
        for (int j = 0; j < 8; j++) Hc = fmaf(totA[j], Hc, totV[j]);
        carryH = Hc;
        __syncthreads();
    }
}

// ---------------------------------------------------------------------------
extern "C" void kernel_launch(void* const* d_in, const int* in_sizes, int n_in,
                              void* d_out, int out_size) {
    const float* x = (const float*)d_in[0];   // (8, 512, 8192)
    const float* W = (const float*)d_in[1];   // (1024, 512, 1)
    float* out = (float*)d_out;               // (8, 512, 8192)

    normalize_w_kernel<<<O_OUT, 128>>>(W);

    dim3 grid(L_SEQ / BN, O_OUT / BM, BATCH);
    gemm_kernel<<<grid, 512>>>(x);

    scan_kernel<<<BATCH * 512, 256>>>(out);
}

// round 6
// speedup vs baseline: 3.3381x; 3.3381x over previous
#include <cuda_runtime.h>
#include <cuda_fp16.h>
#include <cstdint>

#define L_SEQ 8192
#define D_IN  512
#define O_OUT 1024
#define BATCH 8
#define KEXP  (3 * D_IN)     // 1536 expanded K

// Scratch (device-global: allocation-free per harness rules)
__device__ float  g_fb[(size_t)BATCH * O_OUT * L_SEQ];     // 256 MB
__device__ __half g_aexp[(size_t)O_OUT * KEXP];            // 3 MB, [o][3k+{hi,lo,hi}]

// ---------------------------------------------------------------------------
// Kernel 1: normalize W rows, split into fp16 hi/lo, K-expand [hi, lo, hi]
// A is pre-scaled by 2048 (undone in GEMM epilogue) so lo stays fp16-normal.
// ---------------------------------------------------------------------------
#define A_SCALE 2048.0f

__global__ void normalize_w_kernel(const float* __restrict__ W) {
    int o = blockIdx.x;          // 1024 rows
    int tid = threadIdx.x;       // 128 threads
    const float* row = W + (size_t)o * D_IN;
    float s = 0.f;
    for (int i = tid; i < D_IN; i += 128) { float w = row[i]; s = fmaf(w, w, s); }
    #pragma unroll
    for (int off = 16; off; off >>= 1) s += __shfl_xor_sync(0xffffffffu, s, off);
    __shared__ float red[4];
    if ((tid & 31) == 0) red[tid >> 5] = s;
    __syncthreads();
    float tot = red[0] + red[1] + red[2] + red[3];
    // Wn = W / (EPS + ||W||/sqrt(fan)) / sqrt(fan) = W / (EPS*sqrt(fan) + ||W||)
    float inv = A_SCALE / (1e-4f * sqrtf((float)D_IN) + sqrtf(tot));
    for (int i = tid; i < D_IN; i += 128) {
        float wn = row[i] * inv;
        __half hi = __float2half_rn(wn);
        __half lo = __float2half_rn(wn - __half2float(hi));
        size_t base = (size_t)o * KEXP + 3 * i;
        g_aexp[base + 0] = hi;
        g_aexp[base + 1] = lo;
        g_aexp[base + 2] = hi;
    }
}

// ---------------------------------------------------------------------------
// Kernel 2: GEMM fb = Wn @ x as ONE fp16 GEMM over expanded K'=1536.
// A expanded [hi,lo,hi] (gmem, precomputed); B expanded [hi,hi,lo] at staging.
// CTA tile 128x256, 256 threads (8 warps, 2x4, warp tile 64x64),
// double-buffered smem, ldmatrix.x4 fragments, m16n8k16 HMMA.
// ---------------------------------------------------------------------------
#define GBM 128
#define GBN 256
#define KSTEP 16                  // original K per iter (48 expanded)
#define ITERS (D_IN / KSTEP)      // 32

#define LDA 56                    // halves per A smem row (48 + pad 8)
#define LDB 264                   // halves per B smem row (256 + pad 8)
#define A_BYTES (GBM * LDA * 2)   // 14336
#define B_BYTES (48 * LDB * 2)    // 25344
#define STAGE (A_BYTES + B_BYTES) // 39680
#define SMEM_TOTAL (2 * STAGE)    // 79360

__device__ __forceinline__ uint32_t smem_u32(const void* p) {
    uint32_t a;
    asm("{ .reg .u64 t; cvta.to.shared.u64 t, %1; cvt.u32.u64 %0, t; }" : "=r"(a) : "l"(p));
    return a;
}

__device__ __forceinline__ void ldsm_x4(uint32_t* r, uint32_t addr) {
    asm volatile("ldmatrix.sync.aligned.m8n8.x4.shared.b16 {%0,%1,%2,%3}, [%4];"
        : "=r"(r[0]), "=r"(r[1]), "=r"(r[2]), "=r"(r[3]) : "r"(addr));
}
__device__ __forceinline__ void ldsm_x4_t(uint32_t* r, uint32_t addr) {
    asm volatile("ldmatrix.sync.aligned.m8n8.x4.trans.shared.b16 {%0,%1,%2,%3}, [%4];"
        : "=r"(r[0]), "=r"(r[1]), "=r"(r[2]), "=r"(r[3]) : "r"(addr));
}
__device__ __forceinline__ void mma_f16(float* c, const uint32_t* a, uint32_t b0, uint32_t b1) {
    asm volatile("mma.sync.aligned.m16n8k16.row.col.f32.f16.f16.f32 "
        "{%0,%1,%2,%3}, {%4,%5,%6,%7}, {%8,%9}, {%0,%1,%2,%3};"
        : "+f"(c[0]), "+f"(c[1]), "+f"(c[2]), "+f"(c[3])
        : "r"(a[0]), "r"(a[1]), "r"(a[2]), "r"(a[3]), "r"(b0), "r"(b1));
}

__device__ __forceinline__ uint32_t pack_h2(float a, float b) {
    __half2 h = __floats2half2_rn(a, b);
    return *(uint32_t*)&h;
}

__global__ void __launch_bounds__(256, 1) gemm_f16_kernel(const float* __restrict__ x) {
    extern __shared__ char smem[];
    const uint32_t sb = smem_u32(smem);

    const int tid   = threadIdx.x;
    const int lane  = tid & 31;
    const int warp  = tid >> 5;
    const int warpM = warp >> 2;            // 0..1
    const int warpN = warp & 3;             // 0..3
    const int m0 = blockIdx.x * GBM;        // M fastest -> x stripe L2 reuse
    const int n0 = blockIdx.y * GBN;
    const int b  = blockIdx.z;
    const float* xb = x + (size_t)b * D_IN * L_SEQ;

    float acc[4][8][4];
    #pragma unroll
    for (int mt = 0; mt < 4; mt++)
        #pragma unroll
        for (int nn = 0; nn < 8; nn++)
            #pragma unroll
            for (int i = 0; i < 4; i++) acc[mt][nn][i] = 0.f;

    // prefetch registers
    float4 aReg[3], bReg[4];

    // A load mapping: 128 rows x 48 halves = 768 float4 loads / 256 thr = 3 each
    const int arow[3] = { (tid + 0)   / 6, (tid + 256) / 6, (tid + 512) / 6 };
    const int ac8[3]  = { (tid + 0)   % 6, (tid + 256) % 6, (tid + 512) % 6 };
    // B load mapping: 16 k-rows x 256 n = 1024 float4 / 256 thr = 4 each
    const int bkr = tid >> 6;               // 0..3 (+4 per j)
    const int bnq = tid & 63;

    {   // it = 0
        #pragma unroll
        for (int j = 0; j < 3; j++)
            aReg[j] = *(const float4*)(g_aexp + (size_t)(m0 + arow[j]) * KEXP + ac8[j] * 8);
        #pragma unroll
        for (int j = 0; j < 4; j++)
            bReg[j] = *(const float4*)(xb + (size_t)(bkr + j * 4) * L_SEQ + n0 + bnq * 4);
    }

    #pragma unroll 1
    for (int it = 0; it < ITERS; ++it) {
        char* bp = smem + (it & 1) * STAGE;
        const uint32_t stg = sb + (it & 1) * STAGE;

        // ---- store staged tiles ----
        #pragma unroll
        for (int j = 0; j < 3; j++)
            *(float4*)(bp + arow[j] * (LDA * 2) + ac8[j] * 16) = aReg[j];
        #pragma unroll
        for (int j = 0; j < 4; j++) {
            float4 v = bReg[j];
            __half hx = __float2half_rn(v.x), hy = __float2half_rn(v.y);
            __half hz = __float2half_rn(v.z), hw = __float2half_rn(v.w);
            uint2 hi2 = make_uint2(pack_h2(__half2float(hx), __half2float(hy)),
                                   pack_h2(__half2float(hz), __half2float(hw)));
            uint2 lo2 = make_uint2(pack_h2(v.x - __half2float(hx), v.y - __half2float(hy)),
                                   pack_h2(v.z - __half2float(hz), v.w - __half2float(hw)));
            char* r0 = bp + A_BYTES + (size_t)(3 * (bkr + j * 4)) * (LDB * 2) + bnq * 8;
            *(uint2*)(r0)                 = hi2;   // slot 0: Bhi
            *(uint2*)(r0 + LDB * 2)       = hi2;   // slot 1: Bhi
            *(uint2*)(r0 + 2 * (LDB * 2)) = lo2;   // slot 2: Blo
        }
        __syncthreads();

        // ---- prefetch next iter ----
        if (it + 1 < ITERS) {
            const int k0 = (it + 1) * KSTEP;
            #pragma unroll
            for (int j = 0; j < 3; j++)
                aReg[j] = *(const float4*)(g_aexp + (size_t)(m0 + arow[j]) * KEXP
                                           + (it + 1) * 48 + ac8[j] * 8);
            #pragma unroll
            for (int j = 0; j < 4; j++)
                bReg[j] = *(const float4*)(xb + (size_t)(k0 + bkr + j * 4) * L_SEQ + n0 + bnq * 4);
        }

        // ---- compute: 3 x k16 chunks of the 48 expanded rows ----
        const uint32_t aBase = stg;
        const uint32_t bBase = stg + A_BYTES;
        #pragma unroll
        for (int kk = 0; kk < 3; kk++) {
            uint32_t af[4][4];
            #pragma unroll
            for (int mt = 0; mt < 4; mt++) {
                int row = warpM * 64 + mt * 16 + (lane & 15);
                int col = kk * 16 + (lane >> 4) * 8;
                ldsm_x4(af[mt], aBase + (row * LDA + col) * 2);
            }
            uint32_t bf[4][4];
            #pragma unroll
            for (int ng = 0; ng < 4; ng++) {
                int krow = kk * 16 + (lane & 15);
                int col  = warpN * 64 + ng * 16 + (lane >> 4) * 8;
                ldsm_x4_t(bf[ng], bBase + (krow * LDB + col) * 2);
            }
            #pragma unroll
            for (int mt = 0; mt < 4; mt++)
                #pragma unroll
                for (int ng = 0; ng < 4; ng++) {
                    mma_f16(acc[mt][2 * ng + 0], af[mt], bf[ng][0], bf[ng][1]);
                    mma_f16(acc[mt][2 * ng + 1], af[mt], bf[ng][2], bf[ng][3]);
                }
        }
    }

    // ---- epilogue (undo A_SCALE) ----
    const float sc = 1.0f / A_SCALE;
    float* fbb = g_fb + (size_t)b * O_OUT * L_SEQ;
    #pragma unroll
    for (int mt = 0; mt < 4; mt++) {
        int row = m0 + warpM * 64 + mt * 16 + (lane >> 2);
        #pragma unroll
        for (int nn = 0; nn < 8; nn++) {
            int col = n0 + warpN * 64 + nn * 8 + (lane & 3) * 2;
            *(float2*)&fbb[(size_t)row * L_SEQ + col] =
                make_float2(acc[mt][nn][0] * sc, acc[mt][nn][1] * sc);
            *(float2*)&fbb[(size_t)(row + 8) * L_SEQ + col] =
                make_float2(acc[mt][nn][2] * sc, acc[mt][nn][3] * sc);
        }
    }
}

// ---------------------------------------------------------------------------
// Kernel 3: parallel linear-recurrence scan (fwd + bwd), H_t = a*H_{t-1} + v
// ---------------------------------------------------------------------------
__device__ __forceinline__ void gate(float h, float g, float& a, float& v) {
    float en = expf(-fabsf(g));                 // e^{-|g|}
    float q  = rsqrtf(fmaf(en, en, 1.0f));      // 1/sqrt(1+en^2)
    float eq = en * q;
    bool pos = (g >= 0.f);
    a = pos ? eq : q;           // sigma(-g)*sqrt(1+sech g)
    v = (pos ? q : eq) * h;     // sigma(g)*sqrt(1+sech g)*h
}

__global__ void __launch_bounds__(256) scan_kernel(float* __restrict__ out) {
    const int sid = blockIdx.x;            // 0..4095
    const int b   = sid >> 9;
    const int rem = sid & 511;
    const int dir = rem >> 8;              // 0 fwd, 1 bwd
    const int ch  = rem & 255;

    const float* hp = g_fb + ((size_t)b * O_OUT + (size_t)dir * 512 + ch) * L_SEQ;
    const float* gp = hp + (size_t)256 * L_SEQ;
    float* op = out + ((size_t)b * 512 + (size_t)dir * 256 + ch) * L_SEQ;

    const int tid = threadIdx.x;
    const int lane = tid & 31;
    const int warp = tid >> 5;

    __shared__ float totA[8], totV[8];
    float carryH = 0.f;

    #pragma unroll 1
    for (int s = 0; s < L_SEQ / 1024; ++s) {
        const int base = s * 1024 + tid * 4;
        float4 h4, g4;
        if (dir == 0) {
            h4 = *(const float4*)(hp + base);
            g4 = *(const float4*)(gp + base);
        } else {
            int gi = L_SEQ - 4 - base;
            float4 th = *(const float4*)(hp + gi);
            float4 tg = *(const float4*)(gp + gi);
            h4 = make_float4(th.w, th.z, th.y, th.x);
            g4 = make_float4(tg.w, tg.z, tg.y, tg.x);
        }

        float a[4], v[4];
        gate(h4.x, g4.x, a[0], v[0]);
        gate(h4.y, g4.y, a[1], v[1]);
        gate(h4.z, g4.z, a[2], v[2]);
        gate(h4.w, g4.w, a[3], v[3]);

        float A = a[0], V = v[0];
        #pragma unroll
        for (int i = 1; i < 4; i++) { V = fmaf(a[i], V, v[i]); A *= a[i]; }

        #pragma unroll
        for (int off = 1; off < 32; off <<= 1) {
            float Au = __shfl_up_sync(0xffffffffu, A, off);
            float Vu = __shfl_up_sync(0xffffffffu, V, off);
            if (lane >= off) { V = fmaf(A, Vu, V); A *= Au; }
        }
        if (lane == 31) { totA[warp] = A; totV[warp] = V; }
        __syncthreads();

        float Hp = carryH;
        for (int j = 0; j < warp; j++) Hp = fmaf(totA[j], Hp, totV[j]);

        float Ae = __shfl_up_sync(0xffffffffu, A, 1);
        float Ve = __shfl_up_sync(0xffffffffu, V, 1);
        float H = (lane == 0) ? Hp : fmaf(Ae, Hp, Ve);

        float o0, o1, o2, o3;
        H = fmaf(a[0], H, v[0]); o0 = H;
        H = fmaf(a[1], H, v[1]); o1 = H;
        H = fmaf(a[2], H, v[2]); o2 = H;
        H = fmaf(a[3], H, v[3]); o3 = H;

        if (dir == 0) {
            *(float4*)(op + base) = make_float4(o0, o1, o2, o3);
        } else {
            *(float4*)(op + (L_SEQ - 4 - base)) = make_float4(o3, o2, o1, o0);
        }

        float Hc = carryH;
        #pragma unroll
        for (int j = 0; j < 8; j++) Hc = fmaf(totA[j], Hc, totV[j]);
        carryH = Hc;
        __syncthreads();
    }
}

// ---------------------------------------------------------------------------
extern "C" void kernel_launch(void* const* d_in, const int* in_sizes, int n_in,
                              void* d_out, int out_size) {
    const float* x = (const float*)d_in[0];   // (8, 512, 8192)
    const float* W = (const float*)d_in[1];   // (1024, 512, 1)
    float* out = (float*)d_out;               // (8, 512, 8192)

    static int smem_set = 0;
    if (!smem_set) {
        cudaFuncSetAttribute(gemm_f16_kernel,
                             cudaFuncAttributeMaxDynamicSharedMemorySize, SMEM_TOTAL);
        smem_set = 1;
    }

    normalize_w_kernel<<<O_OUT, 128>>>(W);

    dim3 grid(O_OUT / GBM, L_SEQ / GBN, BATCH);   // M fastest for x L2 reuse
    gemm_f16_kernel<<<grid, 256, SMEM_TOTAL>>>(x);

    scan_kernel<<<BATCH * 512, 256>>>(out);
}

// round 8
// speedup vs baseline: 5.8672x; 1.7577x over previous
#include <cuda_runtime.h>
#include <cuda_fp16.h>
#include <cstdint>

#define L_SEQ 8192
#define D_IN  512
#define O_OUT 1024
#define BATCH 8

// Scratch (device-global: allocation-free per harness rules)
__device__ __half g_fb[(size_t)BATCH * O_OUT * L_SEQ];   // 128 MB (fp16)
__device__ __half g_xh[(size_t)BATCH * D_IN * L_SEQ];    // 64 MB  (x in fp16)
__device__ __half g_ah[(size_t)O_OUT * D_IN];            // 1 MB   (Wn in fp16)

// ---------------------------------------------------------------------------
// Kernel 1: normalize W rows -> fp16
// ---------------------------------------------------------------------------
__global__ void normalize_w_kernel(const float* __restrict__ W) {
    int o = blockIdx.x;          // 1024 rows
    int tid = threadIdx.x;       // 128 threads
    const float* row = W + (size_t)o * D_IN;
    float s = 0.f;
    for (int i = tid; i < D_IN; i += 128) { float w = row[i]; s = fmaf(w, w, s); }
    #pragma unroll
    for (int off = 16; off; off >>= 1) s += __shfl_xor_sync(0xffffffffu, s, off);
    __shared__ float red[4];
    if ((tid & 31) == 0) red[tid >> 5] = s;
    __syncthreads();
    float tot = red[0] + red[1] + red[2] + red[3];
    // Wn = W / (EPS + ||W||/sqrt(fan)) / sqrt(fan) = W / (EPS*sqrt(fan) + ||W||)
    float inv = 1.0f / (1e-4f * sqrtf((float)D_IN) + sqrtf(tot));
    for (int i = tid; i < D_IN; i += 128)
        g_ah[(size_t)o * D_IN + i] = __float2half_rn(row[i] * inv);
}

// ---------------------------------------------------------------------------
// Kernel 2: convert x (f32 -> fp16), 8 elems/thread
// ---------------------------------------------------------------------------
__global__ void __launch_bounds__(256) convert_x_kernel(const float* __restrict__ x) {
    size_t i = ((size_t)blockIdx.x * 256 + threadIdx.x) * 8;
    float4 v0 = *(const float4*)(x + i);
    float4 v1 = *(const float4*)(x + i + 4);
    __half2 h0 = __floats2half2_rn(v0.x, v0.y);
    __half2 h1 = __floats2half2_rn(v0.z, v0.w);
    __half2 h2 = __floats2half2_rn(v1.x, v1.y);
    __half2 h3 = __floats2half2_rn(v1.z, v1.w);
    uint4 u = make_uint4(*(uint32_t*)&h0, *(uint32_t*)&h1, *(uint32_t*)&h2, *(uint32_t*)&h3);
    *(uint4*)(g_xh + i) = u;
}

// ---------------------------------------------------------------------------
// Kernel 3: GEMM fb = Wn @ x, plain fp16, K=512.
// CTA tile 128x256, 512 threads (16 warps 2x8, warp tile 64x32),
// cp.async 4-stage pipeline, ldmatrix.x4, m16n8k16 HMMA, fp16 epilogue.
// ---------------------------------------------------------------------------
#define GBM 128
#define GBN 256
#define GBK 32
#define ITERS (D_IN / GBK)        // 16
#define STAGES 4

#define LDA 40                    // halves per A smem row (32 + pad 8)
#define LDB 264                   // halves per B smem row (256 + pad 8)
#define A_SZ (GBM * LDA * 2)      // 10240
#define B_SZ (GBK * LDB * 2)      // 16896
#define STAGE_SZ (A_SZ + B_SZ)    // 27136
#define SMEM_TOTAL (STAGES * STAGE_SZ)  // 108544

__device__ __forceinline__ uint32_t smem_u32(const void* p) {
    uint32_t a;
    asm("{ .reg .u64 t; cvta.to.shared.u64 t, %1; cvt.u32.u64 %0, t; }" : "=r"(a) : "l"(p));
    return a;
}
__device__ __forceinline__ void cp16(uint32_t dst, const void* src) {
    asm volatile("cp.async.cg.shared.global [%0], [%1], 16;" :: "r"(dst), "l"(src));
}
__device__ __forceinline__ void ldsm_x4(uint32_t* r, uint32_t addr) {
    asm volatile("ldmatrix.sync.aligned.m8n8.x4.shared.b16 {%0,%1,%2,%3}, [%4];"
        : "=r"(r[0]), "=r"(r[1]), "=r"(r[2]), "=r"(r[3]) : "r"(addr));
}
__device__ __forceinline__ void ldsm_x4_t(uint32_t* r, uint32_t addr) {
    asm volatile("ldmatrix.sync.aligned.m8n8.x4.trans.shared.b16 {%0,%1,%2,%3}, [%4];"
        : "=r"(r[0]), "=r"(r[1]), "=r"(r[2]), "=r"(r[3]) : "r"(addr));
}
__device__ __forceinline__ void mma_f16(float* c, const uint32_t* a, uint32_t b0, uint32_t b1) {
    asm volatile("mma.sync.aligned.m16n8k16.row.col.f32.f16.f16.f32 "
        "{%0,%1,%2,%3}, {%4,%5,%6,%7}, {%8,%9}, {%0,%1,%2,%3};"
        : "+f"(c[0]), "+f"(c[1]), "+f"(c[2]), "+f"(c[3])
        : "r"(a[0]), "r"(a[1]), "r"(a[2]), "r"(a[3]), "r"(b0), "r"(b1));
}

__device__ __forceinline__ void load_stage(uint32_t sb, const __half* gx,
                                           int m0, int n0, int ld, int tid) {
    const uint32_t st = sb + (uint32_t)(ld & (STAGES - 1)) * STAGE_SZ;
    const int k0 = ld * GBK;
    // A: 128 rows x 32 halves = 512 x 16B chunks, 1 per thread
    {
        int row = tid >> 2, ch = tid & 3;
        cp16(st + row * (LDA * 2) + ch * 16,
             g_ah + (size_t)(m0 + row) * D_IN + k0 + ch * 8);
    }
    // B: 32 rows x 256 halves = 1024 x 16B chunks, 2 per thread
    #pragma unroll
    for (int j = 0; j < 2; j++) {
        int idx = tid + j * 512;
        int row = idx >> 5, ch = idx & 31;
        cp16(st + A_SZ + row * (LDB * 2) + ch * 16,
             gx + (size_t)(k0 + row) * L_SEQ + n0 + ch * 8);
    }
}

__global__ void __launch_bounds__(512, 1) gemm_f16_kernel() {
    extern __shared__ char smem[];
    const uint32_t sb = smem_u32(smem);

    const int tid  = threadIdx.x;
    const int lane = tid & 31;
    const int warp = tid >> 5;
    const int wm = warp >> 3;               // 0..1  (64-row slab)
    const int wn = warp & 7;                // 0..7  (32-col slab)
    const int m0 = blockIdx.x * GBM;        // M fastest -> x stripe L2 reuse
    const int n0 = blockIdx.y * GBN;
    const int b  = blockIdx.z;
    const __half* gx = g_xh + (size_t)b * D_IN * L_SEQ;

    float acc[4][4][4];
    #pragma unroll
    for (int mt = 0; mt < 4; mt++)
        #pragma unroll
        for (int nn = 0; nn < 4; nn++)
            #pragma unroll
            for (int i = 0; i < 4; i++) acc[mt][nn][i] = 0.f;

    // prologue: fill 3 stages
    #pragma unroll
    for (int s = 0; s < STAGES - 1; s++) {
        load_stage(sb, gx, m0, n0, s, tid);
        asm volatile("cp.async.commit_group;");
    }

    #pragma unroll 1
    for (int it = 0; it < ITERS; ++it) {
        asm volatile("cp.async.wait_group %0;" :: "n"(STAGES - 2));
        __syncthreads();

        if (it + STAGES - 1 < ITERS)
            load_stage(sb, gx, m0, n0, it + STAGES - 1, tid);
        asm volatile("cp.async.commit_group;");   // always commit: keeps group count fixed

        const uint32_t st = sb + (uint32_t)(it & (STAGES - 1)) * STAGE_SZ;
        #pragma unroll
        for (int kk = 0; kk < 2; kk++) {
            uint32_t af[4][4];
            #pragma unroll
            for (int mt = 0; mt < 4; mt++) {
                int row = wm * 64 + mt * 16 + (lane & 15);
                int col = kk * 16 + (lane >> 4) * 8;
                ldsm_x4(af[mt], st + (row * LDA + col) * 2);
            }
            uint32_t bf[2][4];
            #pragma unroll
            for (int ng = 0; ng < 2; ng++) {
                int krow = kk * 16 + (lane & 15);
                int col  = wn * 32 + ng * 16 + (lane >> 4) * 8;
                ldsm_x4_t(bf[ng], st + A_SZ + (krow * LDB + col) * 2);
            }
            #pragma unroll
            for (int mt = 0; mt < 4; mt++)
                #pragma unroll
                for (int ng = 0; ng < 2; ng++) {
                    mma_f16(acc[mt][2 * ng + 0], af[mt], bf[ng][0], bf[ng][1]);
                    mma_f16(acc[mt][2 * ng + 1], af[mt], bf[ng][2], bf[ng][3]);
                }
        }
    }

    // epilogue -> g_fb (fp16)
    __half* fbb = g_fb + (size_t)b * O_OUT * L_SEQ;
    #pragma unroll
    for (int mt = 0; mt < 4; mt++) {
        int row = m0 + wm * 64 + mt * 16 + (lane >> 2);
        #pragma unroll
        for (int nn = 0; nn < 4; nn++) {
            int col = n0 + wn * 32 + nn * 8 + (lane & 3) * 2;
            __half2 v01 = __floats2half2_rn(acc[mt][nn][0], acc[mt][nn][1]);
            __half2 v23 = __floats2half2_rn(acc[mt][nn][2], acc[mt][nn][3]);
            *(__half2*)&fbb[(size_t)row * L_SEQ + col]       = v01;
            *(__half2*)&fbb[(size_t)(row + 8) * L_SEQ + col] = v23;
        }
    }
}

// ---------------------------------------------------------------------------
// Kernel 4: parallel linear-recurrence scan (fwd + bwd), H_t = a*H_{t-1} + v
// ---------------------------------------------------------------------------
__device__ __forceinline__ void gate(float h, float g, float& a, float& v) {
    float en = expf(-fabsf(g));                 // e^{-|g|}
    float q  = rsqrtf(fmaf(en, en, 1.0f));      // 1/sqrt(1+en^2)
    float eq = en * q;
    bool pos = (g >= 0.f);
    a = pos ? eq : q;           // sigma(-g)*sqrt(1+sech g)
    v = (pos ? q : eq) * h;     // sigma(g)*sqrt(1+sech g)*h
}

__device__ __forceinline__ float4 load_h4(const __half* p, int rev) {
    uint2 u = *(const uint2*)p;
    __half2* hh = (__half2*)&u;
    float2 p0 = __half22float2(hh[0]);
    float2 p1 = __half22float2(hh[1]);
    if (!rev) return make_float4(p0.x, p0.y, p1.x, p1.y);
    return make_float4(p1.y, p1.x, p0.y, p0.x);
}

__global__ void __launch_bounds__(256) scan_kernel(float* __restrict__ out) {
    const int sid = blockIdx.x;            // 0..4095
    const int b   = sid >> 9;
    const int rem = sid & 511;
    const int dir = rem >> 8;              // 0 fwd, 1 bwd
    const int ch  = rem & 255;

    const __half* hp = g_fb + ((size_t)b * O_OUT + (size_t)dir * 512 + ch) * L_SEQ;
    const __half* gp = hp + (size_t)256 * L_SEQ;
    float* op = out + ((size_t)b * 512 + (size_t)dir * 256 + ch) * L_SEQ;

    const int tid = threadIdx.x;
    const int lane = tid & 31;
    const int warp = tid >> 5;

    __shared__ float totA[8], totV[8];
    float carryH = 0.f;

    #pragma unroll 1
    for (int s = 0; s < L_SEQ / 1024; ++s) {
        const int base = s * 1024 + tid * 4;
        float4 h4, g4;
        if (dir == 0) {
            h4 = load_h4(hp + base, 0);
            g4 = load_h4(gp + base, 0);
        } else {
            int gi = L_SEQ - 4 - base;
            h4 = load_h4(hp + gi, 1);
            g4 = load_h4(gp + gi, 1);
        }

        float a[4], v[4];
        gate(h4.x, g4.x, a[0], v[0]);
        gate(h4.y, g4.y, a[1], v[1]);
        gate(h4.z, g4.z, a[2], v[2]);
        gate(h4.w, g4.w, a[3], v[3]);

        float A = a[0], V = v[0];
        #pragma unroll
        for (int i = 1; i < 4; i++) { V = fmaf(a[i], V, v[i]); A *= a[i]; }

        #pragma unroll
        for (int off = 1; off < 32; off <<= 1) {
            float Au = __shfl_up_sync(0xffffffffu, A, off);
            float Vu = __shfl_up_sync(0xffffffffu, V, off);
            if (lane >= off) { V = fmaf(A, Vu, V); A *= Au; }
        }
        if (lane == 31) { totA[warp] = A; totV[warp] = V; }
        __syncthreads();

        float Hp = carryH;
        for (int j = 0; j < warp; j++) Hp = fmaf(totA[j], Hp, totV[j]);

        float Ae = __shfl_up_sync(0xffffffffu, A, 1);
        float Ve = __shfl_up_sync(0xffffffffu, V, 1);
        float H = (lane == 0) ? Hp : fmaf(Ae, Hp, Ve);

        float o0, o1, o2, o3;
        H = fmaf(a[0], H, v[0]); o0 = H;
        H = fmaf(a[1], H, v[1]); o1 = H;
        H = fmaf(a[2], H, v[2]); o2 = H;
        H = fmaf(a[3], H, v[3]); o3 = H;

        if (dir == 0) {
            *(float4*)(op + base) = make_float4(o0, o1, o2, o3);
        } else {
            *(float4*)(op + (L_SEQ - 4 - base)) = make_float4(o3, o2, o1, o0);
        }

        float Hc = carryH;
        #pragma unroll
        for (int j = 0; j < 8; j++) Hc = fmaf(totA[j], Hc, totV[j]);
        carryH = Hc;
        __syncthreads();
    }
}

// ---------------------------------------------------------------------------
extern "C" void kernel_launch(void* const* d_in, const int* in_sizes, int n_in,
                              void* d_out, int out_size) {
    const float* x = (const float*)d_in[0];   // (8, 512, 8192)
    const float* W = (const float*)d_in[1];   // (1024, 512, 1)
    float* out = (float*)d_out;               // (8, 512, 8192)

    // Idempotent, capture-safe (not a stream op); called unconditionally.
    cudaFuncSetAttribute(gemm_f16_kernel,
                         cudaFuncAttributeMaxDynamicSharedMemorySize, SMEM_TOTAL);

    normalize_w_kernel<<<O_OUT, 128>>>(W);
    convert_x_kernel<<<(BATCH * D_IN * L_SEQ) / (256 * 8), 256>>>(x);

    dim3 grid(O_OUT / GBM, L_SEQ / GBN, BATCH);   // M fastest for x L2 reuse
    gemm_f16_kernel<<<grid, 512, SMEM_TOTAL>>>();

    scan_kernel<<<BATCH * 512, 256>>>(out);
}

// round 9
// speedup vs baseline: 5.9570x; 1.0153x over previous
#include <cuda_runtime.h>
#include <cuda_fp16.h>
#include <cstdint>

#define L_SEQ 8192
#define D_IN  512
#define O_OUT 1024
#define BATCH 8

// Scratch (device-global: allocation-free per harness rules)
__device__ __half g_fb[(size_t)BATCH * O_OUT * L_SEQ];   // 128 MB (fp16)
__device__ __half g_ah[(size_t)O_OUT * D_IN];            // 1 MB   (Wn in fp16)

// ---------------------------------------------------------------------------
// Kernel 1: normalize W rows -> fp16
// ---------------------------------------------------------------------------
__global__ void normalize_w_kernel(const float* __restrict__ W) {
    int o = blockIdx.x;          // 1024 rows
    int tid = threadIdx.x;       // 128 threads
    const float* row = W + (size_t)o * D_IN;
    float s = 0.f;
    for (int i = tid; i < D_IN; i += 128) { float w = row[i]; s = fmaf(w, w, s); }
    #pragma unroll
    for (int off = 16; off; off >>= 1) s += __shfl_xor_sync(0xffffffffu, s, off);
    __shared__ float red[4];
    if ((tid & 31) == 0) red[tid >> 5] = s;
    __syncthreads();
    float tot = red[0] + red[1] + red[2] + red[3];
    // Wn = W / (EPS + ||W||/sqrt(fan)) / sqrt(fan) = W / (EPS*sqrt(fan) + ||W||)
    float inv = 1.0f / (1e-4f * sqrtf((float)D_IN) + sqrtf(tot));
    for (int i = tid; i < D_IN; i += 128)
        g_ah[(size_t)o * D_IN + i] = __float2half_rn(row[i] * inv);
}

// ---------------------------------------------------------------------------
// Kernel 2: GEMM fb = Wn @ x, fp16 HMMA, K=512, fused f32->fp16 B conversion.
// CTA tile 128x256, 512 threads (16 warps 2x8, warp tile 64x32).
// A: cp.async 2-stage ring. B: f32 LDG register double-buffer -> cvt -> STS.
// ---------------------------------------------------------------------------
#define GBM 128
#define GBN 256
#define GBK 32
#define ITERS (D_IN / GBK)        // 16

#define LDA 40                    // halves per A smem row (32 + pad 8)
#define LDB 264                   // halves per B smem row (256 + pad 8)
#define A_SZ (GBM * LDA * 2)      // 10240
#define B_SZ (GBK * LDB * 2)      // 16896
#define STAGE_SZ (A_SZ + B_SZ)    // 27136
#define SMEM_TOTAL (2 * STAGE_SZ) // 54272

__device__ __forceinline__ uint32_t smem_u32(const void* p) {
    uint32_t a;
    asm("{ .reg .u64 t; cvta.to.shared.u64 t, %1; cvt.u32.u64 %0, t; }" : "=r"(a) : "l"(p));
    return a;
}
__device__ __forceinline__ void cp16(uint32_t dst, const void* src) {
    asm volatile("cp.async.cg.shared.global [%0], [%1], 16;" :: "r"(dst), "l"(src));
}
__device__ __forceinline__ void ldsm_x4(uint32_t* r, uint32_t addr) {
    asm volatile("ldmatrix.sync.aligned.m8n8.x4.shared.b16 {%0,%1,%2,%3}, [%4];"
        : "=r"(r[0]), "=r"(r[1]), "=r"(r[2]), "=r"(r[3]) : "r"(addr));
}
__device__ __forceinline__ void ldsm_x4_t(uint32_t* r, uint32_t addr) {
    asm volatile("ldmatrix.sync.aligned.m8n8.x4.trans.shared.b16 {%0,%1,%2,%3}, [%4];"
        : "=r"(r[0]), "=r"(r[1]), "=r"(r[2]), "=r"(r[3]) : "r"(addr));
}
__device__ __forceinline__ void mma_f16(float* c, const uint32_t* a, uint32_t b0, uint32_t b1) {
    asm volatile("mma.sync.aligned.m16n8k16.row.col.f32.f16.f16.f32 "
        "{%0,%1,%2,%3}, {%4,%5,%6,%7}, {%8,%9}, {%0,%1,%2,%3};"
        : "+f"(c[0]), "+f"(c[1]), "+f"(c[2]), "+f"(c[3])
        : "r"(a[0]), "r"(a[1]), "r"(a[2]), "r"(a[3]), "r"(b0), "r"(b1));
}

// A stage: 128 rows x 32 halves = 512 x 16B chunks, 1 per thread
__device__ __forceinline__ void load_stage_A(uint32_t sb, int m0, int ld, int tid) {
    const uint32_t st = sb + (uint32_t)(ld & 1) * STAGE_SZ;
    int row = tid >> 2, ch = tid & 3;
    cp16(st + row * (LDA * 2) + ch * 16,
         g_ah + (size_t)(m0 + row) * D_IN + ld * GBK + ch * 8);
}

__global__ void __launch_bounds__(512, 1) gemm_f16_kernel(const float* __restrict__ x) {
    extern __shared__ char smem[];
    const uint32_t sb = smem_u32(smem);

    const int tid  = threadIdx.x;
    const int lane = tid & 31;
    const int warp = tid >> 5;
    const int wm = warp >> 3;               // 0..1  (64-row slab)
    const int wn = warp & 7;                // 0..7  (32-col slab)
    const int m0 = blockIdx.x * GBM;        // M fastest -> x stripe L2 reuse
    const int n0 = blockIdx.y * GBN;
    const int b  = blockIdx.z;
    const float* xb = x + (size_t)b * D_IN * L_SEQ;

    // B load mapping: 32 k-rows x 256 f32 = 2048 x 16B chunks, 4 per thread
    const int brow[4] = { (tid + 0) >> 6, (tid + 512) >> 6, (tid + 1024) >> 6, (tid + 1536) >> 6 };
    const int bch[4]  = { (tid + 0) & 63, (tid + 512) & 63, (tid + 1024) & 63, (tid + 1536) & 63 };

    float acc[4][4][4];
    #pragma unroll
    for (int mt = 0; mt < 4; mt++)
        #pragma unroll
        for (int nn = 0; nn < 4; nn++)
            #pragma unroll
            for (int i = 0; i < 4; i++) acc[mt][nn][i] = 0.f;

    // prologue
    float4 bReg[4];
    #pragma unroll
    for (int j = 0; j < 4; j++)
        bReg[j] = *(const float4*)(xb + (size_t)brow[j] * L_SEQ + n0 + bch[j] * 4);
    load_stage_A(sb, m0, 0, tid);
    asm volatile("cp.async.commit_group;");

    #pragma unroll 1
    for (int it = 0; it < ITERS; ++it) {
        const uint32_t st = sb + (uint32_t)(it & 1) * STAGE_SZ;

        // ---- STS B (convert f32 regs -> fp16 smem) ----
        #pragma unroll
        for (int j = 0; j < 4; j++) {
            float4 v = bReg[j];
            __half2 h0 = __floats2half2_rn(v.x, v.y);
            __half2 h1 = __floats2half2_rn(v.z, v.w);
            *(uint2*)(smem + (it & 1) * STAGE_SZ + A_SZ + brow[j] * (LDB * 2) + bch[j] * 8)
                = make_uint2(*(uint32_t*)&h0, *(uint32_t*)&h1);
        }
        __syncthreads();   // #1: all compute(it-1) done -> safe to write next-stage A/B

        if (it + 1 < ITERS) {
            load_stage_A(sb, m0, it + 1, tid);
            const int k1 = (it + 1) * GBK;
            #pragma unroll
            for (int j = 0; j < 4; j++)
                bReg[j] = *(const float4*)(xb + (size_t)(k1 + brow[j]) * L_SEQ + n0 + bch[j] * 4);
        }
        asm volatile("cp.async.commit_group;");   // always: fixed group count
        asm volatile("cp.async.wait_group 1;");   // A(it) complete
        __syncthreads();   // #2: A(it) + B(it) visible to all

        // ---- compute ----
        #pragma unroll
        for (int kk = 0; kk < 2; kk++) {
            uint32_t af[4][4];
            #pragma unroll
            for (int mt = 0; mt < 4; mt++) {
                int row = wm * 64 + mt * 16 + (lane & 15);
                int col = kk * 16 + (lane >> 4) * 8;
                ldsm_x4(af[mt], st + (row * LDA + col) * 2);
            }
            uint32_t bf[2][4];
            #pragma unroll
            for (int ng = 0; ng < 2; ng++) {
                int krow = kk * 16 + (lane & 15);
                int col  = wn * 32 + ng * 16 + (lane >> 4) * 8;
                ldsm_x4_t(bf[ng], st + A_SZ + (krow * LDB + col) * 2);
            }
            #pragma unroll
            for (int mt = 0; mt < 4; mt++)
                #pragma unroll
                for (int ng = 0; ng < 2; ng++) {
                    mma_f16(acc[mt][2 * ng + 0], af[mt], bf[ng][0], bf[ng][1]);
                    mma_f16(acc[mt][2 * ng + 1], af[mt], bf[ng][2], bf[ng][3]);
                }
        }
    }

    // epilogue -> g_fb (fp16)
    __half* fbb = g_fb + (size_t)b * O_OUT * L_SEQ;
    #pragma unroll
    for (int mt = 0; mt < 4; mt++) {
        int row = m0 + wm * 64 + mt * 16 + (lane >> 2);
        #pragma unroll
        for (int nn = 0; nn < 4; nn++) {
            int col = n0 + wn * 32 + nn * 8 + (lane & 3) * 2;
            __half2 v01 = __floats2half2_rn(acc[mt][nn][0], acc[mt][nn][1]);
            __half2 v23 = __floats2half2_rn(acc[mt][nn][2], acc[mt][nn][3]);
            *(__half2*)&fbb[(size_t)row * L_SEQ + col]       = v01;
            *(__half2*)&fbb[(size_t)(row + 8) * L_SEQ + col] = v23;
        }
    }
}

// ---------------------------------------------------------------------------
// Kernel 3: parallel linear-recurrence scan (fwd + bwd), H_t = a*H_{t-1} + v
// ---------------------------------------------------------------------------
__device__ __forceinline__ void gate(float h, float g, float& a, float& v) {
    float en = __expf(-fabsf(g));               // e^{-|g|} (fast path, ~2 ulp)
    float q  = rsqrtf(fmaf(en, en, 1.0f));      // 1/sqrt(1+en^2)
    float eq = en * q;
    bool pos = (g >= 0.f);
    a = pos ? eq : q;           // sigma(-g)*sqrt(1+sech g)
    v = (pos ? q : eq) * h;     // sigma(g)*sqrt(1+sech g)*h
}

__device__ __forceinline__ float4 load_h4(const __half* p, int rev) {
    uint2 u = *(const uint2*)p;
    __half2* hh = (__half2*)&u;
    float2 p0 = __half22float2(hh[0]);
    float2 p1 = __half22float2(hh[1]);
    if (!rev) return make_float4(p0.x, p0.y, p1.x, p1.y);
    return make_float4(p1.y, p1.x, p0.y, p0.x);
}

__global__ void __launch_bounds__(256) scan_kernel(float* __restrict__ out) {
    const int sid = blockIdx.x;            // 0..4095
    const int b   = sid >> 9;
    const int rem = sid & 511;
    const int dir = rem >> 8;              // 0 fwd, 1 bwd
    const int ch  = rem & 255;

    const __half* hp = g_fb + ((size_t)b * O_OUT + (size_t)dir * 512 + ch) * L_SEQ;
    const __half* gp = hp + (size_t)256 * L_SEQ;
    float* op = out + ((size_t)b * 512 + (size_t)dir * 256 + ch) * L_SEQ;

    const int tid = threadIdx.x;
    const int lane = tid & 31;
    const int warp = tid >> 5;

    __shared__ float totA[8], totV[8];
    float carryH = 0.f;

    #pragma unroll 1
    for (int s = 0; s < L_SEQ / 1024; ++s) {
        const int base = s * 1024 + tid * 4;
        float4 h4, g4;
        if (dir == 0) {
            h4 = load_h4(hp + base, 0);
            g4 = load_h4(gp + base, 0);
        } else {
            int gi = L_SEQ - 4 - base;
            h4 = load_h4(hp + gi, 1);
            g4 = load_h4(gp + gi, 1);
        }

        float a[4], v[4];
        gate(h4.x, g4.x, a[0], v[0]);
        gate(h4.y, g4.y, a[1], v[1]);
        gate(h4.z, g4.z, a[2], v[2]);
        gate(h4.w, g4.w, a[3], v[3]);

        float A = a[0], V = v[0];
        #pragma unroll
        for (int i = 1; i < 4; i++) { V = fmaf(a[i], V, v[i]); A *= a[i]; }

        #pragma unroll
        for (int off = 1; off < 32; off <<= 1) {
            float Au = __shfl_up_sync(0xffffffffu, A, off);
            float Vu = __shfl_up_sync(0xffffffffu, V, off);
            if (lane >= off) { V = fmaf(A, Vu, V); A *= Au; }
        }
        if (lane == 31) { totA[warp] = A; totV[warp] = V; }
        __syncthreads();

        float Hp = carryH;
        for (int j = 0; j < warp; j++) Hp = fmaf(totA[j], Hp, totV[j]);

        float Ae = __shfl_up_sync(0xffffffffu, A, 1);
        float Ve = __shfl_up_sync(0xffffffffu, V, 1);
        float H = (lane == 0) ? Hp : fmaf(Ae, Hp, Ve);

        float o0, o1, o2, o3;
        H = fmaf(a[0], H, v[0]); o0 = H;
        H = fmaf(a[1], H, v[1]); o1 = H;
        H = fmaf(a[2], H, v[2]); o2 = H;
        H = fmaf(a[3], H, v[3]); o3 = H;

        if (dir == 0) {
            *(float4*)(op + base) = make_float4(o0, o1, o2, o3);
        } else {
            *(float4*)(op + (L_SEQ - 4 - base)) = make_float4(o3, o2, o1, o0);
        }

        float Hc = carryH;
        #pragma unroll
        for (int j = 0; j < 8; j++) Hc = fmaf(totA[j], Hc, totV[j]);
        carryH = Hc;
        __syncthreads();
    }
}

// ---------------------------------------------------------------------------
extern "C" void kernel_launch(void* const* d_in, const int* in_sizes, int n_in,
                              void* d_out, int out_size) {
    const float* x = (const float*)d_in[0];   // (8, 512, 8192)
    const float* W = (const float*)d_in[1];   // (1024, 512, 1)
    float* out = (float*)d_out;               // (8, 512, 8192)

    // Idempotent, capture-safe (not a stream op); called unconditionally.
    cudaFuncSetAttribute(gemm_f16_kernel,
                         cudaFuncAttributeMaxDynamicSharedMemorySize, SMEM_TOTAL);

    normalize_w_kernel<<<O_OUT, 128>>>(W);

    dim3 grid(O_OUT / GBM, L_SEQ / GBN, BATCH);   // M fastest for x L2 reuse
    gemm_f16_kernel<<<grid, 512, SMEM_TOTAL>>>(x);

    scan_kernel<<<BATCH * 512, 256>>>(out);
}

// round 10
// speedup vs baseline: 6.0348x; 1.0131x over previous
#include <cuda_runtime.h>
#include <cuda_fp16.h>
#include <cstdint>

#define L_SEQ 8192
#define D_IN  512
#define O_OUT 1024
#define BATCH 8

// Scratch (device-global: allocation-free per harness rules)
__device__ __half g_fb[(size_t)BATCH * O_OUT * L_SEQ];   // 128 MB (fp16)
__device__ __half g_ah[(size_t)O_OUT * D_IN];            // 1 MB   (Wn in fp16)

// ---------------------------------------------------------------------------
// Kernel 1: normalize W rows -> fp16
// ---------------------------------------------------------------------------
__global__ void normalize_w_kernel(const float* __restrict__ W) {
    int o = blockIdx.x;          // 1024 rows
    int tid = threadIdx.x;       // 128 threads
    const float* row = W + (size_t)o * D_IN;
    float s = 0.f;
    for (int i = tid; i < D_IN; i += 128) { float w = row[i]; s = fmaf(w, w, s); }
    #pragma unroll
    for (int off = 16; off; off >>= 1) s += __shfl_xor_sync(0xffffffffu, s, off);
    __shared__ float red[4];
    if ((tid & 31) == 0) red[tid >> 5] = s;
    __syncthreads();
    float tot = red[0] + red[1] + red[2] + red[3];
    // Wn = W / (EPS + ||W||/sqrt(fan)) / sqrt(fan) = W / (EPS*sqrt(fan) + ||W||)
    float inv = 1.0f / (1e-4f * sqrtf((float)D_IN) + sqrtf(tot));
    for (int i = tid; i < D_IN; i += 128)
        g_ah[(size_t)o * D_IN + i] = __float2half_rn(row[i] * inv);
}

// ---------------------------------------------------------------------------
// Kernel 2: GEMM fb = Wn @ x, fp16 HMMA, K=512, fused f32->fp16 B conversion.
// CTA tile 256x128 (tall M tile: only 4 M-CTAs share each x stripe -> halves
// B L2 traffic vs 128-tile). 512 threads, 16 warps as 4x4, warp tile 64x32.
// A: cp.async 2-stage ring (fp16 weights). B: f32 LDG reg buffer -> cvt -> STS.
// ---------------------------------------------------------------------------
#define GBM 256
#define GBN 128
#define GBK 32
#define ITERS (D_IN / GBK)        // 16

#define LDA 40                    // halves per A smem row (32 + pad 8)
#define LDB 136                   // halves per B smem row (128 + pad 8)
#define A_SZ (GBM * LDA * 2)      // 20480
#define B_SZ (GBK * LDB * 2)      // 8704
#define STAGE_SZ (A_SZ + B_SZ)    // 29184
#define SMEM_TOTAL (2 * STAGE_SZ) // 58368

__device__ __forceinline__ uint32_t smem_u32(const void* p) {
    uint32_t a;
    asm("{ .reg .u64 t; cvta.to.shared.u64 t, %1; cvt.u32.u64 %0, t; }" : "=r"(a) : "l"(p));
    return a;
}
__device__ __forceinline__ void cp16(uint32_t dst, const void* src) {
    asm volatile("cp.async.cg.shared.global [%0], [%1], 16;" :: "r"(dst), "l"(src));
}
__device__ __forceinline__ void ldsm_x4(uint32_t* r, uint32_t addr) {
    asm volatile("ldmatrix.sync.aligned.m8n8.x4.shared.b16 {%0,%1,%2,%3}, [%4];"
        : "=r"(r[0]), "=r"(r[1]), "=r"(r[2]), "=r"(r[3]) : "r"(addr));
}
__device__ __forceinline__ void ldsm_x4_t(uint32_t* r, uint32_t addr) {
    asm volatile("ldmatrix.sync.aligned.m8n8.x4.trans.shared.b16 {%0,%1,%2,%3}, [%4];"
        : "=r"(r[0]), "=r"(r[1]), "=r"(r[2]), "=r"(r[3]) : "r"(addr));
}
__device__ __forceinline__ void mma_f16(float* c, const uint32_t* a, uint32_t b0, uint32_t b1) {
    asm volatile("mma.sync.aligned.m16n8k16.row.col.f32.f16.f16.f32 "
        "{%0,%1,%2,%3}, {%4,%5,%6,%7}, {%8,%9}, {%0,%1,%2,%3};"
        : "+f"(c[0]), "+f"(c[1]), "+f"(c[2]), "+f"(c[3])
        : "r"(a[0]), "r"(a[1]), "r"(a[2]), "r"(a[3]), "r"(b0), "r"(b1));
}

// A stage: 256 rows x 32 halves = 1024 x 16B chunks, 2 per thread
__device__ __forceinline__ void load_stage_A(uint32_t sb, int m0, int ld, int tid) {
    const uint32_t st = sb + (uint32_t)(ld & 1) * STAGE_SZ;
    #pragma unroll
    for (int j = 0; j < 2; j++) {
        int idx = tid + j * 512;
        int row = idx >> 2, ch = idx & 3;
        cp16(st + row * (LDA * 2) + ch * 16,
             g_ah + (size_t)(m0 + row) * D_IN + ld * GBK + ch * 8);
    }
}

__global__ void __launch_bounds__(512, 1) gemm_f16_kernel(const float* __restrict__ x) {
    extern __shared__ char smem[];
    const uint32_t sb = smem_u32(smem);

    const int tid  = threadIdx.x;
    const int lane = tid & 31;
    const int warp = tid >> 5;
    const int wm = warp >> 2;               // 0..3  (64-row slab)
    const int wn = warp & 3;                // 0..3  (32-col slab)
    const int m0 = blockIdx.x * GBM;        // M fastest -> x stripe L2 reuse
    const int n0 = blockIdx.y * GBN;
    const int b  = blockIdx.z;
    const float* xb = x + (size_t)b * D_IN * L_SEQ;

    // B load mapping: 32 k-rows x 128 f32 = 1024 x 16B chunks, 2 per thread
    const int brow[2] = { (tid + 0) >> 5, (tid + 512) >> 5 };
    const int bch[2]  = { (tid + 0) & 31, (tid + 512) & 31 };

    float acc[4][4][4];
    #pragma unroll
    for (int mt = 0; mt < 4; mt++)
        #pragma unroll
        for (int nn = 0; nn < 4; nn++)
            #pragma unroll
            for (int i = 0; i < 4; i++) acc[mt][nn][i] = 0.f;

    // prologue
    float4 bReg[2];
    #pragma unroll
    for (int j = 0; j < 2; j++)
        bReg[j] = *(const float4*)(xb + (size_t)brow[j] * L_SEQ + n0 + bch[j] * 4);
    load_stage_A(sb, m0, 0, tid);
    asm volatile("cp.async.commit_group;");

    #pragma unroll 1
    for (int it = 0; it < ITERS; ++it) {
        const uint32_t st = sb + (uint32_t)(it & 1) * STAGE_SZ;

        // ---- STS B (convert f32 regs -> fp16 smem) ----
        #pragma unroll
        for (int j = 0; j < 2; j++) {
            float4 v = bReg[j];
            __half2 h0 = __floats2half2_rn(v.x, v.y);
            __half2 h1 = __floats2half2_rn(v.z, v.w);
            *(uint2*)(smem + (it & 1) * STAGE_SZ + A_SZ + brow[j] * (LDB * 2) + bch[j] * 8)
                = make_uint2(*(uint32_t*)&h0, *(uint32_t*)&h1);
        }
        __syncthreads();   // #1: all compute(it-1) done -> safe to write next-stage A/B

        if (it + 1 < ITERS) {
            load_stage_A(sb, m0, it + 1, tid);
            const int k1 = (it + 1) * GBK;
            #pragma unroll
            for (int j = 0; j < 2; j++)
                bReg[j] = *(const float4*)(xb + (size_t)(k1 + brow[j]) * L_SEQ + n0 + bch[j] * 4);
        }
        asm volatile("cp.async.commit_group;");   // always: fixed group count
        asm volatile("cp.async.wait_group 1;");   // A(it) complete
        __syncthreads();   // #2: A(it) + B(it) visible to all

        // ---- compute ----
        #pragma unroll
        for (int kk = 0; kk < 2; kk++) {
            uint32_t af[4][4];
            #pragma unroll
            for (int mt = 0; mt < 4; mt++) {
                int row = wm * 64 + mt * 16 + (lane & 15);
                int col = kk * 16 + (lane >> 4) * 8;
                ldsm_x4(af[mt], st + (row * LDA + col) * 2);
            }
            uint32_t bf[2][4];
            #pragma unroll
            for (int ng = 0; ng < 2; ng++) {
                int krow = kk * 16 + (lane & 15);
                int col  = wn * 32 + ng * 16 + (lane >> 4) * 8;
                ldsm_x4_t(bf[ng], st + A_SZ + (krow * LDB + col) * 2);
            }
            #pragma unroll
            for (int mt = 0; mt < 4; mt++)
                #pragma unroll
                for (int ng = 0; ng < 2; ng++) {
                    mma_f16(acc[mt][2 * ng + 0], af[mt], bf[ng][0], bf[ng][1]);
                    mma_f16(acc[mt][2 * ng + 1], af[mt], bf[ng][2], bf[ng][3]);
                }
        }
    }

    // epilogue -> g_fb (fp16)
    __half* fbb = g_fb + (size_t)b * O_OUT * L_SEQ;
    #pragma unroll
    for (int mt = 0; mt < 4; mt++) {
        int row = m0 + wm * 64 + mt * 16 + (lane >> 2);
        #pragma unroll
        for (int nn = 0; nn < 4; nn++) {
            int col = n0 + wn * 32 + nn * 8 + (lane & 3) * 2;
            __half2 v01 = __floats2half2_rn(acc[mt][nn][0], acc[mt][nn][1]);
            __half2 v23 = __floats2half2_rn(acc[mt][nn][2], acc[mt][nn][3]);
            *(__half2*)&fbb[(size_t)row * L_SEQ + col]       = v01;
            *(__half2*)&fbb[(size_t)(row + 8) * L_SEQ + col] = v23;
        }
    }
}

// ---------------------------------------------------------------------------
// Kernel 3: parallel linear-recurrence scan (fwd + bwd), H_t = a*H_{t-1} + v
// ---------------------------------------------------------------------------
__device__ __forceinline__ void gate(float h, float g, float& a, float& v) {
    float en = __expf(-fabsf(g));               // e^{-|g|} (fast path, ~2 ulp)
    float q  = rsqrtf(fmaf(en, en, 1.0f));      // 1/sqrt(1+en^2)
    float eq = en * q;
    bool pos = (g >= 0.f);
    a = pos ? eq : q;           // sigma(-g)*sqrt(1+sech g)
    v = (pos ? q : eq) * h;     // sigma(g)*sqrt(1+sech g)*h
}

__device__ __forceinline__ float4 load_h4(const __half* p, int rev) {
    uint2 u = *(const uint2*)p;
    __half2* hh = (__half2*)&u;
    float2 p0 = __half22float2(hh[0]);
    float2 p1 = __half22float2(hh[1]);
    if (!rev) return make_float4(p0.x, p0.y, p1.x, p1.y);
    return make_float4(p1.y, p1.x, p0.y, p0.x);
}

__global__ void __launch_bounds__(256) scan_kernel(float* __restrict__ out) {
    const int sid = blockIdx.x;            // 0..4095
    const int b   = sid >> 9;
    const int rem = sid & 511;
    const int dir = rem >> 8;              // 0 fwd, 1 bwd
    const int ch  = rem & 255;

    const __half* hp = g_fb + ((size_t)b * O_OUT + (size_t)dir * 512 + ch) * L_SEQ;
    const __half* gp = hp + (size_t)256 * L_SEQ;
    float* op = out + ((size_t)b * 512 + (size_t)dir * 256 + ch) * L_SEQ;

    const int tid = threadIdx.x;
    const int lane = tid & 31;
    const int warp = tid >> 5;

    __shared__ float totA[8], totV[8];
    float carryH = 0.f;

    #pragma unroll 1
    for (int s = 0; s < L_SEQ / 1024; ++s) {
        const int base = s * 1024 + tid * 4;
        float4 h4, g4;
        if (dir == 0) {
            h4 = load_h4(hp + base, 0);
            g4 = load_h4(gp + base, 0);
        } else {
            int gi = L_SEQ - 4 - base;
            h4 = load_h4(hp + gi, 1);
            g4 = load_h4(gp + gi, 1);
        }

        float a[4], v[4];
        gate(h4.x, g4.x, a[0], v[0]);
        gate(h4.y, g4.y, a[1], v[1]);
        gate(h4.z, g4.z, a[2], v[2]);
        gate(h4.w, g4.w, a[3], v[3]);

        float A = a[0], V = v[0];
        #pragma unroll
        for (int i = 1; i < 4; i++) { V = fmaf(a[i], V, v[i]); A *= a[i]; }

        #pragma unroll
        for (int off = 1; off < 32; off <<= 1) {
            float Au = __shfl_up_sync(0xffffffffu, A, off);
            float Vu = __shfl_up_sync(0xffffffffu, V, off);
            if (lane >= off) { V = fmaf(A, Vu, V); A *= Au; }
        }
        if (lane == 31) { totA[warp] = A; totV[warp] = V; }
        __syncthreads();

        float Hp = carryH;
        for (int j = 0; j < warp; j++) Hp = fmaf(totA[j], Hp, totV[j]);

        float Ae = __shfl_up_sync(0xffffffffu, A, 1);
        float Ve = __shfl_up_sync(0xffffffffu, V, 1);
        float H = (lane == 0) ? Hp : fmaf(Ae, Hp, Ve);

        float o0, o1, o2, o3;
        H = fmaf(a[0], H, v[0]); o0 = H;
        H = fmaf(a[1], H, v[1]); o1 = H;
        H = fmaf(a[2], H, v[2]); o2 = H;
        H = fmaf(a[3], H, v[3]); o3 = H;

        if (dir == 0) {
            *(float4*)(op + base) = make_float4(o0, o1, o2, o3);
        } else {
            *(float4*)(op + (L_SEQ - 4 - base)) = make_float4(o3, o2, o1, o0);
        }

        float Hc = carryH;
        #pragma unroll
        for (int j = 0; j < 8; j++) Hc = fmaf(totA[j], Hc, totV[j]);
        carryH = Hc;
        __syncthreads();
    }
}

// ---------------------------------------------------------------------------
extern "C" void kernel_launch(void* const* d_in, const int* in_sizes, int n_in,
                              void* d_out, int out_size) {
    const float* x = (const float*)d_in[0];   // (8, 512, 8192)
    const float* W = (const float*)d_in[1];   // (1024, 512, 1)
    float* out = (float*)d_out;               // (8, 512, 8192)

    // Idempotent, capture-safe (not a stream op); called unconditionally.
    cudaFuncSetAttribute(gemm_f16_kernel,
                         cudaFuncAttributeMaxDynamicSharedMemorySize, SMEM_TOTAL);

    normalize_w_kernel<<<O_OUT, 128>>>(W);

    dim3 grid(O_OUT / GBM, L_SEQ / GBN, BATCH);   // M fastest for x L2 reuse
    gemm_f16_kernel<<<grid, 512, SMEM_TOTAL>>>(x);

    scan_kernel<<<BATCH * 512, 256>>>(out);
}

// round 11
// speedup vs baseline: 6.6391x; 1.1001x over previous
#include <cuda_runtime.h>
#include <cuda_fp16.h>
#include <cstdint>

#define L_SEQ 8192
#define D_IN  512
#define O_OUT 1024
#define BATCH 8

// Scratch (device-global: allocation-free per harness rules)
__device__ __half g_fb[(size_t)BATCH * O_OUT * L_SEQ];   // 128 MB (fp16)
__device__ __half g_ah[(size_t)O_OUT * D_IN];            // 1 MB   (Wn in fp16)

// ---------------------------------------------------------------------------
// Kernel 1: normalize W rows -> fp16
// ---------------------------------------------------------------------------
__global__ void normalize_w_kernel(const float* __restrict__ W) {
    int o = blockIdx.x;          // 1024 rows
    int tid = threadIdx.x;       // 128 threads
    const float* row = W + (size_t)o * D_IN;
    float s = 0.f;
    for (int i = tid; i < D_IN; i += 128) { float w = row[i]; s = fmaf(w, w, s); }
    #pragma unroll
    for (int off = 16; off; off >>= 1) s += __shfl_xor_sync(0xffffffffu, s, off);
    __shared__ float red[4];
    if ((tid & 31) == 0) red[tid >> 5] = s;
    __syncthreads();
    float tot = red[0] + red[1] + red[2] + red[3];
    // Wn = W / (EPS + ||W||/sqrt(fan)) / sqrt(fan) = W / (EPS*sqrt(fan) + ||W||)
    float inv = 1.0f / (1e-4f * sqrtf((float)D_IN) + sqrtf(tot));
    for (int i = tid; i < D_IN; i += 128)
        g_ah[(size_t)o * D_IN + i] = __float2half_rn(row[i] * inv);
}

// ---------------------------------------------------------------------------
// Kernel 2: GEMM fb = Wn @ x, fp16 HMMA, K=512, fused f32->fp16 B conversion.
// CTA tile 128x128, 256 threads (8 warps 2x4, warp tile 64x32),
// __launch_bounds__(256, 2) -> 2 CTAs/SM so barrier/LDG stalls of one CTA are
// covered by the sibling CTA's warps (R10 showed 1-CTA occupancy exposed all
// pipeline latency; traffic shaping was a dead end).
// A: cp.async 2-stage ring (fp16 weights). B: f32 LDG reg buffer -> cvt -> STS.
// ---------------------------------------------------------------------------
#define GBM 128
#define GBN 128
#define GBK 32
#define ITERS (D_IN / GBK)        // 16

#define LDA 40                    // halves per A smem row (32 + pad 8)
#define LDB 136                   // halves per B smem row (128 + pad 8)
#define A_SZ (GBM * LDA * 2)      // 10240
#define B_SZ (GBK * LDB * 2)      // 8704
#define STAGE_SZ (A_SZ + B_SZ)    // 18944
#define SMEM_TOTAL (2 * STAGE_SZ) // 37888

__device__ __forceinline__ uint32_t smem_u32(const void* p) {
    uint32_t a;
    asm("{ .reg .u64 t; cvta.to.shared.u64 t, %1; cvt.u32.u64 %0, t; }" : "=r"(a) : "l"(p));
    return a;
}
__device__ __forceinline__ void cp16(uint32_t dst, const void* src) {
    asm volatile("cp.async.cg.shared.global [%0], [%1], 16;" :: "r"(dst), "l"(src));
}
__device__ __forceinline__ void ldsm_x4(uint32_t* r, uint32_t addr) {
    asm volatile("ldmatrix.sync.aligned.m8n8.x4.shared.b16 {%0,%1,%2,%3}, [%4];"
        : "=r"(r[0]), "=r"(r[1]), "=r"(r[2]), "=r"(r[3]) : "r"(addr));
}
__device__ __forceinline__ void ldsm_x4_t(uint32_t* r, uint32_t addr) {
    asm volatile("ldmatrix.sync.aligned.m8n8.x4.trans.shared.b16 {%0,%1,%2,%3}, [%4];"
        : "=r"(r[0]), "=r"(r[1]), "=r"(r[2]), "=r"(r[3]) : "r"(addr));
}
__device__ __forceinline__ void mma_f16(float* c, const uint32_t* a, uint32_t b0, uint32_t b1) {
    asm volatile("mma.sync.aligned.m16n8k16.row.col.f32.f16.f16.f32 "
        "{%0,%1,%2,%3}, {%4,%5,%6,%7}, {%8,%9}, {%0,%1,%2,%3};"
        : "+f"(c[0]), "+f"(c[1]), "+f"(c[2]), "+f"(c[3])
        : "r"(a[0]), "r"(a[1]), "r"(a[2]), "r"(a[3]), "r"(b0), "r"(b1));
}

// A stage: 128 rows x 32 halves = 512 x 16B chunks, 2 per thread
__device__ __forceinline__ void load_stage_A(uint32_t sb, int m0, int ld, int tid) {
    const uint32_t st = sb + (uint32_t)(ld & 1) * STAGE_SZ;
    #pragma unroll
    for (int j = 0; j < 2; j++) {
        int idx = tid + j * 256;
        int row = idx >> 2, ch = idx & 3;
        cp16(st + row * (LDA * 2) + ch * 16,
             g_ah + (size_t)(m0 + row) * D_IN + ld * GBK + ch * 8);
    }
}

__global__ void __launch_bounds__(256, 2) gemm_f16_kernel(const float* __restrict__ x) {
    extern __shared__ char smem[];
    const uint32_t sb = smem_u32(smem);

    const int tid  = threadIdx.x;
    const int lane = tid & 31;
    const int warp = tid >> 5;
    const int wm = warp >> 2;               // 0..1  (64-row slab)
    const int wn = warp & 3;                // 0..3  (32-col slab)
    const int m0 = blockIdx.x * GBM;        // M fastest -> x stripe L2 reuse
    const int n0 = blockIdx.y * GBN;
    const int b  = blockIdx.z;
    const float* xb = x + (size_t)b * D_IN * L_SEQ;

    // B load mapping: 32 k-rows x 128 f32 = 1024 x 16B chunks, 4 per thread
    int brow[4], bch[4];
    #pragma unroll
    for (int j = 0; j < 4; j++) {
        int idx = tid + j * 256;
        brow[j] = idx >> 5;
        bch[j]  = idx & 31;
    }

    float acc[4][4][4];
    #pragma unroll
    for (int mt = 0; mt < 4; mt++)
        #pragma unroll
        for (int nn = 0; nn < 4; nn++)
            #pragma unroll
            for (int i = 0; i < 4; i++) acc[mt][nn][i] = 0.f;

    // prologue
    float4 bReg[4];
    #pragma unroll
    for (int j = 0; j < 4; j++)
        bReg[j] = *(const float4*)(xb + (size_t)brow[j] * L_SEQ + n0 + bch[j] * 4);
    load_stage_A(sb, m0, 0, tid);
    asm volatile("cp.async.commit_group;");

    #pragma unroll 1
    for (int it = 0; it < ITERS; ++it) {
        const uint32_t st = sb + (uint32_t)(it & 1) * STAGE_SZ;

        // ---- STS B (convert f32 regs -> fp16 smem) ----
        #pragma unroll
        for (int j = 0; j < 4; j++) {
            float4 v = bReg[j];
            __half2 h0 = __floats2half2_rn(v.x, v.y);
            __half2 h1 = __floats2half2_rn(v.z, v.w);
            *(uint2*)(smem + (it & 1) * STAGE_SZ + A_SZ + brow[j] * (LDB * 2) + bch[j] * 8)
                = make_uint2(*(uint32_t*)&h0, *(uint32_t*)&h1);
        }
        __syncthreads();   // #1: all compute(it-1) done -> safe to write next-stage A/B

        if (it + 1 < ITERS) {
            load_stage_A(sb, m0, it + 1, tid);
            const int k1 = (it + 1) * GBK;
            #pragma unroll
            for (int j = 0; j < 4; j++)
                bReg[j] = *(const float4*)(xb + (size_t)(k1 + brow[j]) * L_SEQ + n0 + bch[j] * 4);
        }
        asm volatile("cp.async.commit_group;");   // always: fixed group count
        asm volatile("cp.async.wait_group 1;");   // A(it) complete
        __syncthreads();   // #2: A(it) + B(it) visible to all

        // ---- compute ----
        #pragma unroll
        for (int kk = 0; kk < 2; kk++) {
            uint32_t af[4][4];
            #pragma unroll
            for (int mt = 0; mt < 4; mt++) {
                int row = wm * 64 + mt * 16 + (lane & 15);
                int col = kk * 16 + (lane >> 4) * 8;
                ldsm_x4(af[mt], st + (row * LDA + col) * 2);
            }
            uint32_t bf[2][4];
            #pragma unroll
            for (int ng = 0; ng < 2; ng++) {
                int krow = kk * 16 + (lane & 15);
                int col  = wn * 32 + ng * 16 + (lane >> 4) * 8;
                ldsm_x4_t(bf[ng], st + A_SZ + (krow * LDB + col) * 2);
            }
            #pragma unroll
            for (int mt = 0; mt < 4; mt++)
                #pragma unroll
                for (int ng = 0; ng < 2; ng++) {
                    mma_f16(acc[mt][2 * ng + 0], af[mt], bf[ng][0], bf[ng][1]);
                    mma_f16(acc[mt][2 * ng + 1], af[mt], bf[ng][2], bf[ng][3]);
                }
        }
    }

    // epilogue -> g_fb (fp16)
    __half* fbb = g_fb + (size_t)b * O_OUT * L_SEQ;
    #pragma unroll
    for (int mt = 0; mt < 4; mt++) {
        int row = m0 + wm * 64 + mt * 16 + (lane >> 2);
        #pragma unroll
        for (int nn = 0; nn < 4; nn++) {
            int col = n0 + wn * 32 + nn * 8 + (lane & 3) * 2;
            __half2 v01 = __floats2half2_rn(acc[mt][nn][0], acc[mt][nn][1]);
            __half2 v23 = __floats2half2_rn(acc[mt][nn][2], acc[mt][nn][3]);
            *(__half2*)&fbb[(size_t)row * L_SEQ + col]       = v01;
            *(__half2*)&fbb[(size_t)(row + 8) * L_SEQ + col] = v23;
        }
    }
}

// ---------------------------------------------------------------------------
// Kernel 3: parallel linear-recurrence scan (fwd + bwd), H_t = a*H_{t-1} + v
// ---------------------------------------------------------------------------
__device__ __forceinline__ void gate(float h, float g, float& a, float& v) {
    float en = __expf(-fabsf(g));               // e^{-|g|} (fast path, ~2 ulp)
    float q  = rsqrtf(fmaf(en, en, 1.0f));      // 1/sqrt(1+en^2)
    float eq = en * q;
    bool pos = (g >= 0.f);
    a = pos ? eq : q;           // sigma(-g)*sqrt(1+sech g)
    v = (pos ? q : eq) * h;     // sigma(g)*sqrt(1+sech g)*h
}

__device__ __forceinline__ float4 load_h4(const __half* p, int rev) {
    uint2 u = *(const uint2*)p;
    __half2* hh = (__half2*)&u;
    float2 p0 = __half22float2(hh[0]);
    float2 p1 = __half22float2(hh[1]);
    if (!rev) return make_float4(p0.x, p0.y, p1.x, p1.y);
    return make_float4(p1.y, p1.x, p0.y, p0.x);
}

__global__ void __launch_bounds__(256) scan_kernel(float* __restrict__ out) {
    const int sid = blockIdx.x;            // 0..4095
    const int b   = sid >> 9;
    const int rem = sid & 511;
    const int dir = rem >> 8;              // 0 fwd, 1 bwd
    const int ch  = rem & 255;

    const __half* hp = g_fb + ((size_t)b * O_OUT + (size_t)dir * 512 + ch) * L_SEQ;
    const __half* gp = hp + (size_t)256 * L_SEQ;
    float* op = out + ((size_t)b * 512 + (size_t)dir * 256 + ch) * L_SEQ;

    const int tid = threadIdx.x;
    const int lane = tid & 31;
    const int warp = tid >> 5;

    __shared__ float totA[8], totV[8];
    float carryH = 0.f;

    #pragma unroll 1
    for (int s = 0; s < L_SEQ / 1024; ++s) {
        const int base = s * 1024 + tid * 4;
        float4 h4, g4;
        if (dir == 0) {
            h4 = load_h4(hp + base, 0);
            g4 = load_h4(gp + base, 0);
        } else {
            int gi = L_SEQ - 4 - base;
            h4 = load_h4(hp + gi, 1);
            g4 = load_h4(gp + gi, 1);
        }

        float a[4], v[4];
        gate(h4.x, g4.x, a[0], v[0]);
        gate(h4.y, g4.y, a[1], v[1]);
        gate(h4.z, g4.z, a[2], v[2]);
        gate(h4.w, g4.w, a[3], v[3]);

        float A = a[0], V = v[0];
        #pragma unroll
        for (int i = 1; i < 4; i++) { V = fmaf(a[i], V, v[i]); A *= a[i]; }

        #pragma unroll
        for (int off = 1; off < 32; off <<= 1) {
            float Au = __shfl_up_sync(0xffffffffu, A, off);
            float Vu = __shfl_up_sync(0xffffffffu, V, off);
            if (lane >= off) { V = fmaf(A, Vu, V); A *= Au; }
        }
        if (lane == 31) { totA[warp] = A; totV[warp] = V; }
        __syncthreads();

        float Hp = carryH;
        for (int j = 0; j < warp; j++) Hp = fmaf(totA[j], Hp, totV[j]);

        float Ae = __shfl_up_sync(0xffffffffu, A, 1);
        float Ve = __shfl_up_sync(0xffffffffu, V, 1);
        float H = (lane == 0) ? Hp : fmaf(Ae, Hp, Ve);

        float o0, o1, o2, o3;
        H = fmaf(a[0], H, v[0]); o0 = H;
        H = fmaf(a[1], H, v[1]); o1 = H;
        H = fmaf(a[2], H, v[2]); o2 = H;
        H = fmaf(a[3], H, v[3]); o3 = H;

        if (dir == 0) {
            *(float4*)(op + base) = make_float4(o0, o1, o2, o3);
        } else {
            *(float4*)(op + (L_SEQ - 4 - base)) = make_float4(o3, o2, o1, o0);
        }

        float Hc = carryH;
        #pragma unroll
        for (int j = 0; j < 8; j++) Hc = fmaf(totA[j], Hc, totV[j]);
        carryH = Hc;
        __syncthreads();
    }
}

// ---------------------------------------------------------------------------
extern "C" void kernel_launch(void* const* d_in, const int* in_sizes, int n_in,
                              void* d_out, int out_size) {
    const float* x = (const float*)d_in[0];   // (8, 512, 8192)
    const float* W = (const float*)d_in[1];   // (1024, 512, 1)
    float* out = (float*)d_out;               // (8, 512, 8192)

    // Idempotent, capture-safe (not a stream op); called unconditionally.
    cudaFuncSetAttribute(gemm_f16_kernel,
                         cudaFuncAttributeMaxDynamicSharedMemorySize, SMEM_TOTAL);

    normalize_w_kernel<<<O_OUT, 128>>>(W);

    dim3 grid(O_OUT / GBM, L_SEQ / GBN, BATCH);   // M fastest for x L2 reuse
    gemm_f16_kernel<<<grid, 256, SMEM_TOTAL>>>(x);

    scan_kernel<<<BATCH * 512, 256>>>(out);
}